// round 12
// baseline (speedup 1.0000x reference)
#include <cuda_runtime.h>
#include <cuda_fp16.h>
#include <cstdint>
#include <cstddef>

#define NITEMS   50000
#define DIM      64
#define BATCH    1024
#define NCHAN    3
#define MROWS    (NCHAN * BATCH)     // 3072
#define TM       128
#define TN       64
#define NT_N     782                 // NPAD / 64
#define NPAD     (NT_N * TN)         // 50048
#define MT_PER_CTA 8                 // 24 m-tiles / grid.y(3)
#define ROWB     144                 // smem row stride bytes (128 + 16 pad)

#define A_SCALE  512.0f
#define B_SCALE  512.0f
#define OUT_SCALE (1.0f / (A_SCALE * B_SCALE))   // exact 2^-18

// ---------------- fp16 scratch (device globals; no allocs) ------------------
__device__ __half gA[MROWS * DIM];       // round(A * 2^9)   (A = u*w)
__device__ __half gB_hi[NPAD * DIM];     // round(B * 2^9)
__device__ __half gB_lo[NPAD * DIM];     // residual of B * 2^9

// ---------------- smem layout (bytes) ---------------------------------------
#define ATILE_B  (128 * ROWB)        // 18432
#define BTILE_B  (64 * ROWB)         // 9216
#define S_BH     0
#define S_BL     (S_BH + BTILE_B)    // 9216
#define S_A0     (S_BL + BTILE_B)    // 18432
#define S_A1     (S_A0 + ATILE_B)    // 36864
#define S_TOT    (S_A1 + ATILE_B)    // 55296  -> 3 CTAs/SM (165.9 KB)

// ---------------- helpers ----------------------------------------------------
__device__ __forceinline__ uint32_t smem_u32(const void* p) {
    uint32_t a;
    asm("{ .reg .u64 t; cvta.to.shared.u64 t, %1; cvt.u32.u64 %0, t; }" : "=r"(a) : "l"(p));
    return a;
}

#define CP16(dst, src) \
    asm volatile("cp.async.cg.shared.global [%0], [%1], 16;" :: "r"(dst), "l"(src))

#define LDSM4(r, addr)                                                        \
    asm volatile("ldmatrix.sync.aligned.m8n8.x4.shared.b16 {%0,%1,%2,%3}, [%4];" \
        : "=r"((r)[0]), "=r"((r)[1]), "=r"((r)[2]), "=r"((r)[3]) : "r"(addr))

#define MMA(d, a, b0_, b1_)                                                   \
    asm volatile("mma.sync.aligned.m16n8k16.row.col.f32.f16.f16.f32 "         \
        "{%0,%1,%2,%3}, {%4,%5,%6,%7}, {%8,%9}, {%0,%1,%2,%3};"               \
        : "+f"((d)[0]), "+f"((d)[1]), "+f"((d)[2]), "+f"((d)[3])              \
        : "r"((a)[0]), "r"((a)[1]), "r"((a)[2]), "r"((a)[3]),                 \
          "r"(b0_), "r"(b1_))

// fill a [rows x 64] fp16 tile (128B rows) into padded smem via cp.async
__device__ __forceinline__ void fill_tile(uint32_t s, const __half* g,
                                          int tid, int rows)
{
    for (int idx = tid; idx < rows * 8; idx += 256) {
        int row = idx >> 3, c = idx & 7;
        CP16(s + row * ROWB + c * 16, (const char*)g + row * 128 + c * 16);
    }
}

// ---------------- prep: A rounded, B split hi/lo, all scaled by 2^9 ---------
__global__ void gmf_prep(const int* __restrict__ users,
                         const int* __restrict__ items,
                         const float* __restrict__ utab,
                         const float* __restrict__ itab,
                         const float* __restrict__ wv,
                         const float* __restrict__ wc,
                         const float* __restrict__ wb)
{
    int idx = blockIdx.x * 256 + threadIdx.x;
    if (idx < NPAD * DIM) {
        int d = idx & (DIM - 1);
        int i = idx >> 6;
        float v = 0.0f;
        if (i < NITEMS) v = itab[(size_t)items[i] * DIM + d] * B_SCALE;
        __half hi = __float2half_rn(v);
        gB_hi[idx] = hi;
        gB_lo[idx] = __float2half_rn(v - __half2float(hi));
    }
    if (idx < MROWS * DIM) {
        int d = idx & (DIM - 1);
        int row = idx >> 6;
        int j = row >> 10;
        int b = row & (BATCH - 1);
        const float* w = (j == 0) ? wv : ((j == 1) ? wc : wb);
        float a = utab[(size_t)users[b] * DIM + d] * w[d] * A_SCALE;
        gA[idx] = __float2half_rn(a);
    }
}

// ---------------- main GEMM --------------------------------------------------
// C = Ah*Bh^T + Ah*Bl^T  (fp32 acc, K=64); out = C * 2^-18
// grid (782, 3): each CTA owns one N tile of 64, loops 8 M tiles of 128.
// 8 warps: wm 0..3 (32 rows), wn 0..1 (32 cols). Per thread acc 2x4x4 = 32.
__global__ void __launch_bounds__(256, 3)
gmf_mma(float* __restrict__ out)
{
    extern __shared__ char smem[];
    const uint32_t sb = smem_u32(smem);
    const int tid  = threadIdx.x;
    const int wid  = tid >> 5, lane = tid & 31;
    const int wm   = wid & 3;          // m warp 0..3 (32 rows each)
    const int wn   = wid >> 2;         // n warp 0..1 (32 cols each)
    const int l16  = lane & 15;
    const int lh   = lane >> 4;
    const int n0   = blockIdx.x * TN;
    const int mbase = blockIdx.y * MT_PER_CTA;

    // prolog: B tiles + A tile 0 in group 0
    fill_tile(sb + S_BH, gB_hi + (size_t)n0 * DIM, tid, 64);
    fill_tile(sb + S_BL, gB_lo + (size_t)n0 * DIM, tid, 64);
    fill_tile(sb + S_A0, gA + (size_t)(mbase * TM) * DIM, tid, 128);
    asm volatile("cp.async.commit_group;" ::: "memory");

    const uint32_t a_row_off = (32 * wm + l16) * ROWB + lh * 16;
    const uint32_t b_row_off = (32 * wn + l16) * ROWB + lh * 16;

    for (int it = 0; it < MT_PER_CTA; ++it) {
        if (it > 0) __syncthreads();   // prior compute done before buffer reuse
        if (it + 1 < MT_PER_CTA) {
            uint32_t nb = (it + 1) & 1 ? S_A1 : S_A0;
            fill_tile(sb + nb, gA + (size_t)((mbase + it + 1) * TM) * DIM, tid, 128);
            asm volatile("cp.async.commit_group;" ::: "memory");
            asm volatile("cp.async.wait_group 1;" ::: "memory");
        } else {
            asm volatile("cp.async.wait_group 0;" ::: "memory");
        }
        __syncthreads();

        const uint32_t Ah = sb + ((it & 1) ? S_A1 : S_A0);
        const uint32_t Bh = sb + S_BH;
        const uint32_t Bl = sb + S_BL;

        float acc[2][4][4];
#pragma unroll
        for (int mt = 0; mt < 2; ++mt)
#pragma unroll
            for (int nt = 0; nt < 4; ++nt)
#pragma unroll
                for (int q = 0; q < 4; ++q) acc[mt][nt][q] = 0.0f;

#pragma unroll
        for (int c = 0; c < 4; ++c) {
            const uint32_t koff = c * 32;
            uint32_t ah[2][4], bh[4][2], bl[4][2];
#pragma unroll
            for (int mt = 0; mt < 2; ++mt)
                LDSM4(ah[mt], Ah + a_row_off + mt * (16 * ROWB) + koff);
#pragma unroll
            for (int g = 0; g < 2; ++g) {
                uint32_t bo = b_row_off + g * (16 * ROWB) + koff;
                uint32_t r[4];
                LDSM4(r, Bh + bo);
                bh[2 * g][0] = r[0]; bh[2 * g][1] = r[2];
                bh[2 * g + 1][0] = r[1]; bh[2 * g + 1][1] = r[3];
                LDSM4(r, Bl + bo);
                bl[2 * g][0] = r[0]; bl[2 * g][1] = r[2];
                bl[2 * g + 1][0] = r[1]; bl[2 * g + 1][1] = r[3];
            }
#pragma unroll
            for (int mt = 0; mt < 2; ++mt)
#pragma unroll
                for (int nt = 0; nt < 4; ++nt) {
                    MMA(acc[mt][nt], ah[mt], bh[nt][0], bh[nt][1]);
                    MMA(acc[mt][nt], ah[mt], bl[nt][0], bl[nt][1]);
                }
        }

        // epilogue: rescale by exact 2^-18, float2 stores (32B sectors/quad)
        const int m0 = (mbase + it) * TM;
        const int r0 = m0 + 32 * wm + (lane >> 2);
        const int cb = n0 + 32 * wn + 2 * (lane & 3);
#pragma unroll
        for (int mt = 0; mt < 2; ++mt) {
#pragma unroll
            for (int nt = 0; nt < 4; ++nt) {
                int col = cb + 8 * nt;
                if (col < NITEMS) {
                    int row = r0 + 16 * mt;
                    float2 v0 = make_float2(acc[mt][nt][0] * OUT_SCALE,
                                            acc[mt][nt][1] * OUT_SCALE);
                    float2 v1 = make_float2(acc[mt][nt][2] * OUT_SCALE,
                                            acc[mt][nt][3] * OUT_SCALE);
                    *(float2*)(out + (size_t)row * NITEMS + col) = v0;
                    *(float2*)(out + (size_t)(row + 8) * NITEMS + col) = v1;
                }
            }
        }
    }
}

// ---------------------------------------------------------------------------
// Inputs: 0 users i32[1024], 1 items i32[50000], 2 dropout (unused),
//         3 user_table f32[100000,64], 4 item_table f32[50000,64],
//         5 wv f32[64,1], 6 wc f32[64,1], 7 wb f32[64,1]
// Output: f32 [3][1024][50000]
// ---------------------------------------------------------------------------
extern "C" void kernel_launch(void* const* d_in, const int* in_sizes, int n_in,
                              void* d_out, int out_size)
{
    const int*   users = (const int*)d_in[0];
    const int*   items = (const int*)d_in[1];
    const float* utab  = (const float*)d_in[3];
    const float* itab  = (const float*)d_in[4];
    const float* wv    = (const float*)d_in[5];
    const float* wc    = (const float*)d_in[6];
    const float* wb    = (const float*)d_in[7];
    float* out = (float*)d_out;

    gmf_prep<<<(NPAD * DIM + 255) / 256, 256>>>(users, items, utab, itab, wv, wc, wb);

    cudaFuncSetAttribute(gmf_mma, cudaFuncAttributeMaxDynamicSharedMemorySize, S_TOT);
    dim3 grid(NT_N, 3);
    gmf_mma<<<grid, 256, S_TOT>>>(out);
}

// round 13
// speedup vs baseline: 1.2770x; 1.2770x over previous
#include <cuda_runtime.h>
#include <cuda_fp16.h>
#include <cstdint>
#include <cstddef>

#define NITEMS   50000
#define DIM      64
#define BATCH    1024
#define NCHAN    3
#define MROWS    (NCHAN * BATCH)     // 3072
#define TM       128
#define TN       128
#define NT_N     391                 // ceil(50000/128)
#define NPAD     (NT_N * 128)        // 50048
#define MT_PER_CTA 8                 // 24 m-tiles / grid.y(3)
#define ROWB     144                 // smem row stride bytes (128 + 16 pad)

#define A_SCALE  512.0f
#define B_SCALE  512.0f
#define OUT_SCALE (1.0f / (A_SCALE * B_SCALE))   // exact 2^-18

// ---------------- fp16 scratch (device globals; no allocs) ------------------
__device__ __half gA[MROWS * DIM];       // round(A * 2^9)   (A = u*w)
__device__ __half gB_hi[NPAD * DIM];     // round(B * 2^9)
__device__ __half gB_lo[NPAD * DIM];     // residual of B * 2^9

// ---------------- smem layout (bytes) ---------------------------------------
#define TILE_B   (128 * ROWB)        // 18432 per tile
#define S_BH     0
#define S_BL     (S_BH + TILE_B)     // 18432
#define S_A0     (S_BL + TILE_B)     // 36864
#define S_A1     (S_A0 + TILE_B)     // 55296
#define S_TOT    (S_A1 + TILE_B)     // 73728  -> 2 CTAs/SM

// ---------------- helpers ----------------------------------------------------
__device__ __forceinline__ uint32_t smem_u32(const void* p) {
    uint32_t a;
    asm("{ .reg .u64 t; cvta.to.shared.u64 t, %1; cvt.u32.u64 %0, t; }" : "=r"(a) : "l"(p));
    return a;
}

#define CP16(dst, src) \
    asm volatile("cp.async.cg.shared.global [%0], [%1], 16;" :: "r"(dst), "l"(src))

#define LDSM4(r, addr)                                                        \
    asm volatile("ldmatrix.sync.aligned.m8n8.x4.shared.b16 {%0,%1,%2,%3}, [%4];" \
        : "=r"((r)[0]), "=r"((r)[1]), "=r"((r)[2]), "=r"((r)[3]) : "r"(addr))

#define MMA(d, a, b0_, b1_)                                                   \
    asm volatile("mma.sync.aligned.m16n8k16.row.col.f32.f16.f16.f32 "         \
        "{%0,%1,%2,%3}, {%4,%5,%6,%7}, {%8,%9}, {%0,%1,%2,%3};"               \
        : "+f"((d)[0]), "+f"((d)[1]), "+f"((d)[2]), "+f"((d)[3])              \
        : "r"((a)[0]), "r"((a)[1]), "r"((a)[2]), "r"((a)[3]),                 \
          "r"(b0_), "r"(b1_))

// fill one 128x64 fp16 tile (128B rows) into padded smem via cp.async
__device__ __forceinline__ void fill_one(uint32_t s, const __half* g, int tid)
{
    for (int idx = tid; idx < 1024; idx += 256) {
        int row = idx >> 3, c = idx & 7;
        CP16(s + row * ROWB + c * 16, (const char*)g + row * 128 + c * 16);
    }
}

// ---------------- prep: A rounded, B split hi/lo, all scaled by 2^9 ---------
__global__ void gmf_prep(const int* __restrict__ users,
                         const int* __restrict__ items,
                         const float* __restrict__ utab,
                         const float* __restrict__ itab,
                         const float* __restrict__ wv,
                         const float* __restrict__ wc,
                         const float* __restrict__ wb)
{
    int idx = blockIdx.x * 256 + threadIdx.x;
    if (idx < NPAD * DIM) {
        int d = idx & (DIM - 1);
        int i = idx >> 6;
        float v = 0.0f;
        if (i < NITEMS) v = itab[(size_t)items[i] * DIM + d] * B_SCALE;
        __half hi = __float2half_rn(v);
        gB_hi[idx] = hi;
        gB_lo[idx] = __float2half_rn(v - __half2float(hi));
    }
    if (idx < MROWS * DIM) {
        int d = idx & (DIM - 1);
        int row = idx >> 6;
        int j = row >> 10;
        int b = row & (BATCH - 1);
        const float* w = (j == 0) ? wv : ((j == 1) ? wc : wb);
        float a = utab[(size_t)users[b] * DIM + d] * w[d] * A_SCALE;
        gA[idx] = __float2half_rn(a);
    }
}

// ---------------- main GEMM --------------------------------------------------
// C = Ah*Bh^T + Ah*Bl^T  (fp32 acc, K=64); out = C * 2^-18
// grid (391, 3): each CTA owns one N tile of 128, loops 8 M tiles of 128.
// Mainloop: all A frags preloaded; B frags double-buffered across 16 flat
// steps (4 k-chunks x 4 n-groups) so LDSM latency hides under MMA issue.
__global__ void __launch_bounds__(256, 2)
gmf_mma(float* __restrict__ out)
{
    extern __shared__ char smem[];
    const uint32_t sb = smem_u32(smem);
    const int tid  = threadIdx.x;
    const int wid  = tid >> 5, lane = tid & 31;
    const int wm   = wid & 3;          // m warp 0..3 (32 rows each)
    const int wn   = wid >> 2;         // n warp 0..1 (64 cols each)
    const int l16  = lane & 15;
    const int lh   = lane >> 4;
    const int n0   = blockIdx.x * TN;
    const int mbase = blockIdx.y * MT_PER_CTA;

    // prolog: B tiles + A tile 0 in group 0
    fill_one(sb + S_BH, gB_hi + (size_t)n0 * DIM, tid);
    fill_one(sb + S_BL, gB_lo + (size_t)n0 * DIM, tid);
    fill_one(sb + S_A0, gA + (size_t)(mbase * TM) * DIM, tid);
    asm volatile("cp.async.commit_group;" ::: "memory");

    const uint32_t a_row_off = (32 * wm + l16) * ROWB + lh * 16;
    const uint32_t b_row_off = (64 * wn + l16) * ROWB + lh * 16;
    const uint32_t Bh = sb + S_BH;
    const uint32_t Bl = sb + S_BL;

    for (int it = 0; it < MT_PER_CTA; ++it) {
        if (it > 0) __syncthreads();   // prior compute done before buffer reuse
        if (it + 1 < MT_PER_CTA) {
            uint32_t nb = (it + 1) & 1 ? S_A1 : S_A0;
            fill_one(sb + nb, gA + (size_t)((mbase + it + 1) * TM) * DIM, tid);
            asm volatile("cp.async.commit_group;" ::: "memory");
            asm volatile("cp.async.wait_group 1;" ::: "memory");
        } else {
            asm volatile("cp.async.wait_group 0;" ::: "memory");
        }
        __syncthreads();

        const uint32_t Ah = sb + ((it & 1) ? S_A1 : S_A0);

        float acc[2][8][4];
#pragma unroll
        for (int mt = 0; mt < 2; ++mt)
#pragma unroll
            for (int nt = 0; nt < 8; ++nt)
#pragma unroll
                for (int q = 0; q < 4; ++q) acc[mt][nt][q] = 0.0f;

        // ---- preload ALL A fragments for K=64 (8 LDSM4, 32 regs) ----
        uint32_t ah[4][2][4];
#pragma unroll
        for (int c = 0; c < 4; ++c)
#pragma unroll
            for (int mt = 0; mt < 2; ++mt)
                LDSM4(ah[c][mt], Ah + a_row_off + mt * (16 * ROWB) + c * 32);

        // ---- flat 16-step loop, B frags double-buffered --------------
        // step s: chunk = s>>2 (k offset), g = s&3 (16-col group)
        uint32_t bhf[2][2][2], blf[2][2][2];   // [parity][ntg][pair]
        {
            uint32_t r[4];
            LDSM4(r, Bh + b_row_off);          // step 0: chunk0, g0
            bhf[0][0][0] = r[0]; bhf[0][0][1] = r[2];
            bhf[0][1][0] = r[1]; bhf[0][1][1] = r[3];
            LDSM4(r, Bl + b_row_off);
            blf[0][0][0] = r[0]; blf[0][0][1] = r[2];
            blf[0][1][0] = r[1]; blf[0][1][1] = r[3];
        }
#pragma unroll
        for (int s = 0; s < 16; ++s) {
            const int cur = s & 1, nxt = cur ^ 1;
            if (s + 1 < 16) {
                const int c1 = (s + 1) >> 2, g1 = (s + 1) & 3;
                const uint32_t bo = b_row_off + g1 * (16 * ROWB) + c1 * 32;
                uint32_t r[4];
                LDSM4(r, Bh + bo);
                bhf[nxt][0][0] = r[0]; bhf[nxt][0][1] = r[2];
                bhf[nxt][1][0] = r[1]; bhf[nxt][1][1] = r[3];
                LDSM4(r, Bl + bo);
                blf[nxt][0][0] = r[0]; blf[nxt][0][1] = r[2];
                blf[nxt][1][0] = r[1]; blf[nxt][1][1] = r[3];
            }
            const int c = s >> 2, g = s & 3;
#pragma unroll
            for (int mt = 0; mt < 2; ++mt)
#pragma unroll
                for (int ntg = 0; ntg < 2; ++ntg) {
                    const int nt = 2 * g + ntg;
                    MMA(acc[mt][nt], ah[c][mt], bhf[cur][ntg][0], bhf[cur][ntg][1]);
                    MMA(acc[mt][nt], ah[c][mt], blf[cur][ntg][0], blf[cur][ntg][1]);
                }
        }

        // epilogue: rescale by exact 2^-18, float2 stores
        const int m0 = (mbase + it) * TM;
        const int r0 = m0 + 32 * wm + (lane >> 2);
        const int cb = n0 + 64 * wn + 2 * (lane & 3);
#pragma unroll
        for (int mt = 0; mt < 2; ++mt) {
#pragma unroll
            for (int nt = 0; nt < 8; ++nt) {
                int col = cb + 8 * nt;
                if (col < NITEMS) {
                    int row = r0 + 16 * mt;
                    float2 v0 = make_float2(acc[mt][nt][0] * OUT_SCALE,
                                            acc[mt][nt][1] * OUT_SCALE);
                    float2 v1 = make_float2(acc[mt][nt][2] * OUT_SCALE,
                                            acc[mt][nt][3] * OUT_SCALE);
                    *(float2*)(out + (size_t)row * NITEMS + col) = v0;
                    *(float2*)(out + (size_t)(row + 8) * NITEMS + col) = v1;
                }
            }
        }
    }
}

// ---------------------------------------------------------------------------
// Inputs: 0 users i32[1024], 1 items i32[50000], 2 dropout (unused),
//         3 user_table f32[100000,64], 4 item_table f32[50000,64],
//         5 wv f32[64,1], 6 wc f32[64,1], 7 wb f32[64,1]
// Output: f32 [3][1024][50000]
// ---------------------------------------------------------------------------
extern "C" void kernel_launch(void* const* d_in, const int* in_sizes, int n_in,
                              void* d_out, int out_size)
{
    const int*   users = (const int*)d_in[0];
    const int*   items = (const int*)d_in[1];
    const float* utab  = (const float*)d_in[3];
    const float* itab  = (const float*)d_in[4];
    const float* wv    = (const float*)d_in[5];
    const float* wc    = (const float*)d_in[6];
    const float* wb    = (const float*)d_in[7];
    float* out = (float*)d_out;

    gmf_prep<<<(NPAD * DIM + 255) / 256, 256>>>(users, items, utab, itab, wv, wc, wb);

    cudaFuncSetAttribute(gmf_mma, cudaFuncAttributeMaxDynamicSharedMemorySize, S_TOT);
    dim3 grid(NT_N, 3);
    gmf_mma<<<grid, 256, S_TOT>>>(out);
}

// round 16
// speedup vs baseline: 1.7902x; 1.4019x over previous
#include <cuda_runtime.h>
#include <cuda_fp16.h>
#include <cstdint>
#include <cstddef>

#define NITEMS   50000
#define DIM      64
#define BATCH    1024
#define NCHAN    3
#define MROWS    (NCHAN * BATCH)     // 3072
#define TM       128
#define TN       128
#define NT_N     391                 // ceil(50000/128)
#define NPAD     (NT_N * 128)        // 50048
#define MT_PER_CTA 8                 // 24 m-tiles / grid.y(3)
#define ROWB     144                 // smem row stride bytes (128 + 16 pad)

#define A_SCALE  512.0f
#define B_SCALE  512.0f
#define OUT_SCALE (1.0f / (A_SCALE * B_SCALE))   // exact 2^-18

// ---------------- fp16 scratch (device globals; no allocs) ------------------
__device__ __half gA[MROWS * DIM];       // round(A * 2^9)   (A = u*w)
__device__ __half gB[NPAD * DIM];        // round(B * 2^9)

// ---------------- smem layout (bytes) ---------------------------------------
#define TILE_B   (128 * ROWB)        // 18432 per tile
#define S_B      0
#define S_A0     (S_B + TILE_B)      // 18432
#define S_A1     (S_A0 + TILE_B)     // 36864
#define S_TOT    (S_A1 + TILE_B)     // 55296  -> 2 CTAs/SM easily

// ---------------- helpers ----------------------------------------------------
__device__ __forceinline__ uint32_t smem_u32(const void* p) {
    uint32_t a;
    asm("{ .reg .u64 t; cvta.to.shared.u64 t, %1; cvt.u32.u64 %0, t; }" : "=r"(a) : "l"(p));
    return a;
}

#define CP16(dst, src) \
    asm volatile("cp.async.cg.shared.global [%0], [%1], 16;" :: "r"(dst), "l"(src))

#define LDSM4(r, addr)                                                        \
    asm volatile("ldmatrix.sync.aligned.m8n8.x4.shared.b16 {%0,%1,%2,%3}, [%4];" \
        : "=r"((r)[0]), "=r"((r)[1]), "=r"((r)[2]), "=r"((r)[3]) : "r"(addr))

#define MMA(d, a, b0_, b1_)                                                   \
    asm volatile("mma.sync.aligned.m16n8k16.row.col.f32.f16.f16.f32 "         \
        "{%0,%1,%2,%3}, {%4,%5,%6,%7}, {%8,%9}, {%0,%1,%2,%3};"               \
        : "+f"((d)[0]), "+f"((d)[1]), "+f"((d)[2]), "+f"((d)[3])              \
        : "r"((a)[0]), "r"((a)[1]), "r"((a)[2]), "r"((a)[3]),                 \
          "r"(b0_), "r"(b1_))

// fill one 128x64 fp16 tile (128B rows) into padded smem via cp.async
__device__ __forceinline__ void fill_one(uint32_t s, const __half* g, int tid)
{
    for (int idx = tid; idx < 1024; idx += 256) {
        int row = idx >> 3, c = idx & 7;
        CP16(s + row * ROWB + c * 16, (const char*)g + row * 128 + c * 16);
    }
}

// ---------------- prep: A, B rounded to fp16, scaled by 2^9 -----------------
__global__ void gmf_prep(const int* __restrict__ users,
                         const int* __restrict__ items,
                         const float* __restrict__ utab,
                         const float* __restrict__ itab,
                         const float* __restrict__ wv,
                         const float* __restrict__ wc,
                         const float* __restrict__ wb)
{
    int idx = blockIdx.x * 256 + threadIdx.x;
    if (idx < NPAD * DIM) {
        int d = idx & (DIM - 1);
        int i = idx >> 6;
        float v = 0.0f;
        if (i < NITEMS) v = itab[(size_t)items[i] * DIM + d] * B_SCALE;
        gB[idx] = __float2half_rn(v);
    }
    if (idx < MROWS * DIM) {
        int d = idx & (DIM - 1);
        int row = idx >> 6;
        int j = row >> 10;
        int b = row & (BATCH - 1);
        const float* w = (j == 0) ? wv : ((j == 1) ? wc : wb);
        float a = utab[(size_t)users[b] * DIM + d] * w[d] * A_SCALE;
        gA[idx] = __float2half_rn(a);
    }
}

// ---------------- main GEMM --------------------------------------------------
// C = Ah*Bh^T  (fp32 acc, K=64); out = C * 2^-18
// grid (391, 3): each CTA owns one N tile of 128, loops 8 M tiles of 128.
__global__ void __launch_bounds__(256, 2)
gmf_mma(float* __restrict__ out)
{
    extern __shared__ char smem[];
    const uint32_t sb = smem_u32(smem);
    const int tid  = threadIdx.x;
    const int wid  = tid >> 5, lane = tid & 31;
    const int wm   = wid & 3;          // m warp 0..3 (32 rows each)
    const int wn   = wid >> 2;         // n warp 0..1 (64 cols each)
    const int l16  = lane & 15;
    const int lh   = lane >> 4;
    const int n0   = blockIdx.x * TN;
    const int mbase = blockIdx.y * MT_PER_CTA;

    // prolog: B tile + A tile 0 in group 0
    fill_one(sb + S_B, gB + (size_t)n0 * DIM, tid);
    fill_one(sb + S_A0, gA + (size_t)(mbase * TM) * DIM, tid);
    asm volatile("cp.async.commit_group;" ::: "memory");

    const uint32_t a_row_off = (32 * wm + l16) * ROWB + lh * 16;
    const uint32_t b_row_off = (64 * wn + l16) * ROWB + lh * 16;
    const uint32_t Bs = sb + S_B;

    for (int it = 0; it < MT_PER_CTA; ++it) {
        if (it > 0) __syncthreads();   // prior compute done before buffer reuse
        if (it + 1 < MT_PER_CTA) {
            uint32_t nb = (it + 1) & 1 ? S_A1 : S_A0;
            fill_one(sb + nb, gA + (size_t)((mbase + it + 1) * TM) * DIM, tid);
            asm volatile("cp.async.commit_group;" ::: "memory");
            asm volatile("cp.async.wait_group 1;" ::: "memory");
        } else {
            asm volatile("cp.async.wait_group 0;" ::: "memory");
        }
        __syncthreads();

        const uint32_t Ah = sb + ((it & 1) ? S_A1 : S_A0);

        float acc[2][8][4];
#pragma unroll
        for (int mt = 0; mt < 2; ++mt)
#pragma unroll
            for (int nt = 0; nt < 8; ++nt)
#pragma unroll
                for (int q = 0; q < 4; ++q) acc[mt][nt][q] = 0.0f;

#pragma unroll
        for (int c = 0; c < 4; ++c) {
            const uint32_t koff = c * 32;
            uint32_t ah[2][4], bh[8][2];
#pragma unroll
            for (int mt = 0; mt < 2; ++mt)
                LDSM4(ah[mt], Ah + a_row_off + mt * (16 * ROWB) + koff);
#pragma unroll
            for (int g = 0; g < 4; ++g) {
                uint32_t bo = b_row_off + g * (16 * ROWB) + koff;
                uint32_t r[4];
                LDSM4(r, Bs + bo);
                bh[2 * g][0] = r[0]; bh[2 * g][1] = r[2];
                bh[2 * g + 1][0] = r[1]; bh[2 * g + 1][1] = r[3];
            }
#pragma unroll
            for (int mt = 0; mt < 2; ++mt)
#pragma unroll
                for (int nt = 0; nt < 8; ++nt)
                    MMA(acc[mt][nt], ah[mt], bh[nt][0], bh[nt][1]);
        }

        // epilogue: rescale by exact 2^-18, float2 stores
        const int m0 = (mbase + it) * TM;
        const int r0 = m0 + 32 * wm + (lane >> 2);
        const int cb = n0 + 64 * wn + 2 * (lane & 3);
#pragma unroll
        for (int mt = 0; mt < 2; ++mt) {
#pragma unroll
            for (int nt = 0; nt < 8; ++nt) {
                int col = cb + 8 * nt;
                if (col < NITEMS) {
                    int row = r0 + 16 * mt;
                    float2 v0 = make_float2(acc[mt][nt][0] * OUT_SCALE,
                                            acc[mt][nt][1] * OUT_SCALE);
                    float2 v1 = make_float2(acc[mt][nt][2] * OUT_SCALE,
                                            acc[mt][nt][3] * OUT_SCALE);
                    *(float2*)(out + (size_t)row * NITEMS + col) = v0;
                    *(float2*)(out + (size_t)(row + 8) * NITEMS + col) = v1;
                }
            }
        }
    }
}

// ---------------------------------------------------------------------------
// Inputs: 0 users i32[1024], 1 items i32[50000], 2 dropout (unused),
//         3 user_table f32[100000,64], 4 item_table f32[50000,64],
//         5 wv f32[64,1], 6 wc f32[64,1], 7 wb f32[64,1]
// Output: f32 [3][1024][50000]
// ---------------------------------------------------------------------------
extern "C" void kernel_launch(void* const* d_in, const int* in_sizes, int n_in,
                              void* d_out, int out_size)
{
    const int*   users = (const int*)d_in[0];
    const int*   items = (const int*)d_in[1];
    const float* utab  = (const float*)d_in[3];
    const float* itab  = (const float*)d_in[4];
    const float* wv    = (const float*)d_in[5];
    const float* wc    = (const float*)d_in[6];
    const float* wb    = (const float*)d_in[7];
    float* out = (float*)d_out;

    gmf_prep<<<(NPAD * DIM + 255) / 256, 256>>>(users, items, utab, itab, wv, wc, wb);

    cudaFuncSetAttribute(gmf_mma, cudaFuncAttributeMaxDynamicSharedMemorySize, S_TOT);
    dim3 grid(NT_N, 3);
    gmf_mma<<<grid, 256, S_TOT>>>(out);
}

// round 17
// speedup vs baseline: 1.8921x; 1.0569x over previous
#include <cuda_runtime.h>
#include <cuda_fp16.h>
#include <cstdint>
#include <cstddef>

#define NITEMS   50000
#define DIM      64
#define BATCH    1024
#define NCHAN    3
#define MROWS    (NCHAN * BATCH)     // 3072
#define TM       128
#define TN       128
#define NT_N     391                 // ceil(50000/128)
#define NPAD     (NT_N * 128)        // 50048
#define MT_PER_CTA 8                 // 24 m-tiles / grid.y(3)
#define ROWB     144                 // smem row stride bytes (128 + 16 pad)
#define NTHR     512

#define A_SCALE  512.0f
#define B_SCALE  512.0f
#define OUT_SCALE (1.0f / (A_SCALE * B_SCALE))   // exact 2^-18

// ---------------- fp16 scratch (device globals; no allocs) ------------------
__device__ __half gA[MROWS * DIM];       // round(A * 2^9)   (A = u*w)
__device__ __half gB[NPAD * DIM];        // round(B * 2^9)

// ---------------- smem layout (bytes) ---------------------------------------
#define TILE_B   (128 * ROWB)        // 18432 per tile
#define S_B      0
#define S_A0     (S_B + TILE_B)      // 18432
#define S_A1     (S_A0 + TILE_B)     // 36864
#define S_TOT    (S_A1 + TILE_B)     // 55296  -> 2 CTAs/SM

// ---------------- helpers ----------------------------------------------------
__device__ __forceinline__ uint32_t smem_u32(const void* p) {
    uint32_t a;
    asm("{ .reg .u64 t; cvta.to.shared.u64 t, %1; cvt.u32.u64 %0, t; }" : "=r"(a) : "l"(p));
    return a;
}

#define CP16(dst, src) \
    asm volatile("cp.async.cg.shared.global [%0], [%1], 16;" :: "r"(dst), "l"(src))

#define LDSM4(r, addr)                                                        \
    asm volatile("ldmatrix.sync.aligned.m8n8.x4.shared.b16 {%0,%1,%2,%3}, [%4];" \
        : "=r"((r)[0]), "=r"((r)[1]), "=r"((r)[2]), "=r"((r)[3]) : "r"(addr))

#define MMA(d, a, b0_, b1_)                                                   \
    asm volatile("mma.sync.aligned.m16n8k16.row.col.f32.f16.f16.f32 "         \
        "{%0,%1,%2,%3}, {%4,%5,%6,%7}, {%8,%9}, {%0,%1,%2,%3};"               \
        : "+f"((d)[0]), "+f"((d)[1]), "+f"((d)[2]), "+f"((d)[3])              \
        : "r"((a)[0]), "r"((a)[1]), "r"((a)[2]), "r"((a)[3]),                 \
          "r"(b0_), "r"(b1_))

// fill one 128x64 fp16 tile (128B rows) into padded smem via cp.async
__device__ __forceinline__ void fill_one(uint32_t s, const __half* g, int tid)
{
    for (int idx = tid; idx < 1024; idx += NTHR) {
        int row = idx >> 3, c = idx & 7;
        CP16(s + row * ROWB + c * 16, (const char*)g + row * 128 + c * 16);
    }
}

// ---------------- prep: A, B rounded to fp16, scaled by 2^9 -----------------
// B path vectorized: one thread handles 4 consecutive d (float4 -> 2x half2)
__global__ void gmf_prep(const int* __restrict__ users,
                         const int* __restrict__ items,
                         const float* __restrict__ utab,
                         const float* __restrict__ itab,
                         const float* __restrict__ wv,
                         const float* __restrict__ wc,
                         const float* __restrict__ wb)
{
    int idx = blockIdx.x * 256 + threadIdx.x;
    if (idx < NPAD * (DIM / 4)) {
        int dq = idx & 15;               // 4-d group
        int i  = idx >> 4;
        float4 f = make_float4(0.f, 0.f, 0.f, 0.f);
        if (i < NITEMS)
            f = *(const float4*)(itab + (size_t)items[i] * DIM + 4 * dq);
        __half2 h0 = __floats2half2_rn(f.x * B_SCALE, f.y * B_SCALE);
        __half2 h1 = __floats2half2_rn(f.z * B_SCALE, f.w * B_SCALE);
        *(__half2*)(gB + (size_t)i * DIM + 4 * dq)     = h0;
        *(__half2*)(gB + (size_t)i * DIM + 4 * dq + 2) = h1;
    }
    if (idx < MROWS * DIM) {
        int d = idx & (DIM - 1);
        int row = idx >> 6;
        int j = row >> 10;
        int b = row & (BATCH - 1);
        const float* w = (j == 0) ? wv : ((j == 1) ? wc : wb);
        float a = utab[(size_t)users[b] * DIM + d] * w[d] * A_SCALE;
        gA[idx] = __float2half_rn(a);
    }
}

// ---------------- main GEMM --------------------------------------------------
// C = Ah*Bh^T  (fp32 acc, K=64); out = C * 2^-18
// grid (391, 3): CTA owns one N tile of 128, loops 8 M tiles of 128.
// 16 warps, warp tile 32x32 (wm 0..3 rows, wn 0..3 cols) -> acc 32 regs.
__global__ void __launch_bounds__(NTHR, 2)
gmf_mma(float* __restrict__ out)
{
    extern __shared__ char smem[];
    const uint32_t sb = smem_u32(smem);
    const int tid  = threadIdx.x;
    const int wid  = tid >> 5, lane = tid & 31;
    const int wm   = wid & 3;          // m warp 0..3 (32 rows each)
    const int wn   = wid >> 2;         // n warp 0..3 (32 cols each)
    const int l16  = lane & 15;
    const int lh   = lane >> 4;
    const int n0   = blockIdx.x * TN;
    const int mbase = blockIdx.y * MT_PER_CTA;

    // prolog: B tile + A tile 0 in group 0
    fill_one(sb + S_B, gB + (size_t)n0 * DIM, tid);
    fill_one(sb + S_A0, gA + (size_t)(mbase * TM) * DIM, tid);
    asm volatile("cp.async.commit_group;" ::: "memory");

    const uint32_t a_row_off = (32 * wm + l16) * ROWB + lh * 16;
    const uint32_t b_row_off = (32 * wn + l16) * ROWB + lh * 16;
    const uint32_t Bs = sb + S_B;

    for (int it = 0; it < MT_PER_CTA; ++it) {
        if (it > 0) __syncthreads();   // prior compute done before buffer reuse
        if (it + 1 < MT_PER_CTA) {
            uint32_t nb = (it + 1) & 1 ? S_A1 : S_A0;
            fill_one(sb + nb, gA + (size_t)((mbase + it + 1) * TM) * DIM, tid);
            asm volatile("cp.async.commit_group;" ::: "memory");
            asm volatile("cp.async.wait_group 1;" ::: "memory");
        } else {
            asm volatile("cp.async.wait_group 0;" ::: "memory");
        }
        __syncthreads();

        const uint32_t Ah = sb + ((it & 1) ? S_A1 : S_A0);

        float acc[2][4][4];
#pragma unroll
        for (int mt = 0; mt < 2; ++mt)
#pragma unroll
            for (int nt = 0; nt < 4; ++nt)
#pragma unroll
                for (int q = 0; q < 4; ++q) acc[mt][nt][q] = 0.0f;

#pragma unroll
        for (int c = 0; c < 4; ++c) {
            const uint32_t koff = c * 32;
            uint32_t ah[2][4];
#pragma unroll
            for (int mt = 0; mt < 2; ++mt)
                LDSM4(ah[mt], Ah + a_row_off + mt * (16 * ROWB) + koff);
#pragma unroll
            for (int g = 0; g < 2; ++g) {   // B streamed: LDSM4 -> 4 MMAs
                uint32_t r[4];
                LDSM4(r, Bs + b_row_off + g * (16 * ROWB) + koff);
#pragma unroll
                for (int mt = 0; mt < 2; ++mt) {
                    MMA(acc[mt][2 * g],     ah[mt], r[0], r[2]);
                    MMA(acc[mt][2 * g + 1], ah[mt], r[1], r[3]);
                }
            }
        }

        // epilogue: rescale by exact 2^-18, float2 stores
        const int m0 = (mbase + it) * TM;
        const int r0 = m0 + 32 * wm + (lane >> 2);
        const int cb = n0 + 32 * wn + 2 * (lane & 3);
#pragma unroll
        for (int mt = 0; mt < 2; ++mt) {
#pragma unroll
            for (int nt = 0; nt < 4; ++nt) {
                int col = cb + 8 * nt;
                if (col < NITEMS) {
                    int row = r0 + 16 * mt;
                    float2 v0 = make_float2(acc[mt][nt][0] * OUT_SCALE,
                                            acc[mt][nt][1] * OUT_SCALE);
                    float2 v1 = make_float2(acc[mt][nt][2] * OUT_SCALE,
                                            acc[mt][nt][3] * OUT_SCALE);
                    *(float2*)(out + (size_t)row * NITEMS + col) = v0;
                    *(float2*)(out + (size_t)(row + 8) * NITEMS + col) = v1;
                }
            }
        }
    }
}

// ---------------------------------------------------------------------------
// Inputs: 0 users i32[1024], 1 items i32[50000], 2 dropout (unused),
//         3 user_table f32[100000,64], 4 item_table f32[50000,64],
//         5 wv f32[64,1], 6 wc f32[64,1], 7 wb f32[64,1]
// Output: f32 [3][1024][50000]
// ---------------------------------------------------------------------------
extern "C" void kernel_launch(void* const* d_in, const int* in_sizes, int n_in,
                              void* d_out, int out_size)
{
    const int*   users = (const int*)d_in[0];
    const int*   items = (const int*)d_in[1];
    const float* utab  = (const float*)d_in[3];
    const float* itab  = (const float*)d_in[4];
    const float* wv    = (const float*)d_in[5];
    const float* wc    = (const float*)d_in[6];
    const float* wb    = (const float*)d_in[7];
    float* out = (float*)d_out;

    gmf_prep<<<(NPAD * (DIM / 4) + 255) / 256, 256>>>(users, items, utab, itab,
                                                      wv, wc, wb);

    cudaFuncSetAttribute(gmf_mma, cudaFuncAttributeMaxDynamicSharedMemorySize, S_TOT);
    dim3 grid(NT_N, 3);
    gmf_mma<<<grid, NTHR, S_TOT>>>(out);
}